// round 7
// baseline (speedup 1.0000x reference)
#include <cuda_runtime.h>
#include <cstdint>

// out = joints @ R + t, R = RX(roll) @ RY(pitch) @ RZ(yaw)

struct Rot {
    float r00, r01, r02;
    float r10, r11, r12;
    float r20, r21, r22;
    float tx, ty, tz;
};

__device__ __forceinline__ Rot make_rot(const float* __restrict__ ori,
                                        const float* __restrict__ trs) {
    float sr, cr, sp, cp, sy, cy;
    sincosf(ori[0], &sr, &cr);
    sincosf(ori[1], &sp, &cp);
    sincosf(ori[2], &sy, &cy);
    Rot R;
    R.r00 = cp * cy;                R.r01 = -cp * sy;               R.r02 = sp;
    R.r10 = cr * sy + sr * sp * cy; R.r11 = cr * cy - sr * sp * sy; R.r12 = -sr * cp;
    R.r20 = sr * sy - cr * sp * cy; R.r21 = sr * cy + cr * sp * sy; R.r22 = cr * cp;
    R.tx = trs[0]; R.ty = trs[1]; R.tz = trs[2];
    return R;
}

__device__ __forceinline__ void xform(const Rot& R, float x, float y, float z,
                                      float& ox, float& oy, float& oz) {
    ox = fmaf(x, R.r00, fmaf(y, R.r10, fmaf(z, R.r20, R.tx)));
    oy = fmaf(x, R.r01, fmaf(y, R.r11, fmaf(z, R.r21, R.ty)));
    oz = fmaf(x, R.r02, fmaf(y, R.r12, fmaf(z, R.r22, R.tz)));
}

__device__ __forceinline__ uint32_t smem_u32(const void* p) {
    uint32_t a;
    asm("{ .reg .u64 t; cvta.to.shared.u64 t, %1; cvt.u32.u64 %0, t; }"
        : "=r"(a) : "l"(p));
    return a;
}

// Transform 3 consecutive float4s (4 points) in place.
__device__ __forceinline__ void xform12(const Rot& R, float4& a, float4& b, float4& c) {
    float4 oa, ob, oc;
    xform(R, a.x, a.y, a.z, oa.x, oa.y, oa.z);
    xform(R, a.w, b.x, b.y, oa.w, ob.x, ob.y);
    xform(R, b.z, b.w, c.x, ob.z, ob.w, oc.x);
    xform(R, c.y, c.z, c.w, oc.y, oc.z, oc.w);
    a = oa; b = ob; c = oc;
}

// Tile = 768 float4 = 12KB = 1024 points. One tile per CTA, single-shot:
// TMA in -> in-place transform -> TMA out. Block = 128 threads so 16 CTAs
// fit per SM (thread cap), doubling in-flight TMA tiles per SM and hiding
// each CTA's store-drain behind its neighbors.
static constexpr int TILE_F4    = 768;
static constexpr int TILE_BYTES = TILE_F4 * 16;  // 12288
static constexpr int BLOCK      = 128;

__global__ void __launch_bounds__(BLOCK)
transform_tile(const float* __restrict__ in, float* __restrict__ out,
               const float* __restrict__ ori, const float* __restrict__ trs,
               int ntiles, int n_pts) {
    __shared__ __align__(16) float4 s[TILE_F4];
    __shared__ __align__(8) uint64_t mbar;

    const int t   = threadIdx.x;
    const int bid = blockIdx.x;

    if (bid >= ntiles) {
        // Tail block: scalar path for points beyond the full tiles.
        const int start = ntiles * (TILE_F4 * 4 / 3);
        const Rot R = make_rot(ori, trs);
        for (int p = start + t; p < n_pts; p += BLOCK) {
            long o = 3L * p;
            float x = in[o], y = in[o + 1], z = in[o + 2];
            float ox, oy, oz;
            xform(R, x, y, z, ox, oy, oz);
            out[o] = ox; out[o + 1] = oy; out[o + 2] = oz;
        }
        return;
    }

    const uint32_t s_addr = smem_u32(s);
    const uint32_t m_addr = smem_u32(&mbar);
    const char* gsrc = (const char*)in + (long)bid * TILE_BYTES;
    char*       gdst = (char*)out      + (long)bid * TILE_BYTES;

    // Thread 0: init barrier and immediately launch the bulk load — no
    // block-wide barrier on the load-issue path.
    if (t == 0) {
        asm volatile("mbarrier.init.shared.b64 [%0], 1;" :: "r"(m_addr) : "memory");
        asm volatile("fence.proxy.async.shared::cta;" ::: "memory");
        asm volatile("mbarrier.arrive.expect_tx.shared.b64 _, [%0], %1;"
                     :: "r"(m_addr), "r"(TILE_BYTES) : "memory");
        asm volatile("cp.async.bulk.shared::cta.global.mbarrier::complete_tx::bytes "
                     "[%0], [%1], %2, [%3];"
                     :: "r"(s_addr), "l"(gsrc), "r"(TILE_BYTES), "r"(m_addr)
                     : "memory");
    }

    // Rotation matrix (MUFU) overlaps the bulk load.
    const Rot R = make_rot(ori, trs);

    // Make barrier init visible to all threads before they wait on it.
    __syncthreads();

    // Wait for TMA completion (phase 0).
    {
        uint32_t done;
        asm volatile(
            "{\n\t.reg .pred p;\n\t"
            "mbarrier.try_wait.parity.acquire.cta.shared::cta.b64 p, [%1], 0;\n\t"
            "selp.b32 %0, 1, 0, p;\n\t}"
            : "=r"(done) : "r"(m_addr) : "memory");
        if (!done) {
            asm volatile(
                "{\n\t.reg .pred P1;\n\t"
                "W%=:\n\t"
                "mbarrier.try_wait.parity.acquire.cta.shared::cta.b64 P1, [%0], 0, 0x989680;\n\t"
                "@P1 bra.uni D%=;\n\t"
                "bra.uni W%=;\n\t"
                "D%=:\n\t}"
                :: "r"(m_addr) : "memory");
        }
    }

    // Each thread: two groups of 3 consecutive float4s (8 points total).
    // 48B stride -> conflict-free LDS.128/STS.128. In-place transform.
    {
        float4 a = s[3 * t + 0], b = s[3 * t + 1], c = s[3 * t + 2];
        float4 d = s[384 + 3 * t + 0], e = s[384 + 3 * t + 1], f = s[384 + 3 * t + 2];
        xform12(R, a, b, c);
        xform12(R, d, e, f);
        s[3 * t + 0] = a; s[3 * t + 1] = b; s[3 * t + 2] = c;
        s[384 + 3 * t + 0] = d; s[384 + 3 * t + 1] = e; s[384 + 3 * t + 2] = f;
    }
    __syncthreads();

    if (t == 0) {
        asm volatile("fence.proxy.async.shared::cta;" ::: "memory");
        asm volatile("cp.async.bulk.global.shared::cta.bulk_group [%0], [%1], %2;"
                     :: "l"(gdst), "r"(s_addr), "r"(TILE_BYTES) : "memory");
        asm volatile("cp.async.bulk.commit_group;" ::: "memory");
        asm volatile("cp.async.bulk.wait_group 0;" ::: "memory");
        asm volatile("mbarrier.inval.shared.b64 [%0];" :: "r"(m_addr) : "memory");
    }
}

extern "C" void kernel_launch(void* const* d_in, const int* in_sizes, int n_in,
                              void* d_out, int out_size) {
    const float* joints = (const float*)d_in[0];
    const float* ori    = (const float*)d_in[1];
    const float* trs    = (const float*)d_in[2];
    float* out = (float*)d_out;

    const int n_floats = in_sizes[0];
    const int n_points = n_floats / 3;

    const int floats_per_tile = TILE_F4 * 4;          // 3072 (= 1024 points)
    const int ntiles = n_floats / floats_per_tile;    // 13780 exact for this shape
    const int tail_pts = n_points - ntiles * (floats_per_tile / 3);

    const int grid = ntiles + (tail_pts > 0 ? 1 : 0);
    if (grid > 0) {
        transform_tile<<<grid, BLOCK>>>(joints, out, ori, trs, ntiles, n_points);
    }
}

// round 8
// speedup vs baseline: 1.0006x; 1.0006x over previous
#include <cuda_runtime.h>

// out = joints @ R + t, R = RX(roll) @ RY(pitch) @ RZ(yaw)
// R rows (row i multiplies p[i], since result is p @ R):
//   r0 = [ cp*cy,            -cp*sy,            sp    ]
//   r1 = [ cr*sy + sr*sp*cy,  cr*cy - sr*sp*sy, -sr*cp]
//   r2 = [ sr*sy - cr*sp*cy,  sr*cy + cr*sp*sy,  cr*cp]

struct Rot {
    float r00, r01, r02;
    float r10, r11, r12;
    float r20, r21, r22;
    float tx, ty, tz;
};

__device__ __forceinline__ Rot make_rot(const float* __restrict__ ori,
                                        const float* __restrict__ trs) {
    float sr, cr, sp, cp, sy, cy;
    sincosf(ori[0], &sr, &cr);
    sincosf(ori[1], &sp, &cp);
    sincosf(ori[2], &sy, &cy);
    Rot R;
    R.r00 = cp * cy;                R.r01 = -cp * sy;               R.r02 = sp;
    R.r10 = cr * sy + sr * sp * cy; R.r11 = cr * cy - sr * sp * sy; R.r12 = -sr * cp;
    R.r20 = sr * sy - cr * sp * cy; R.r21 = sr * cy + cr * sp * sy; R.r22 = cr * cp;
    R.tx = trs[0]; R.ty = trs[1]; R.tz = trs[2];
    return R;
}

__device__ __forceinline__ void xform(const Rot& R, float x, float y, float z,
                                      float& ox, float& oy, float& oz) {
    ox = fmaf(x, R.r00, fmaf(y, R.r10, fmaf(z, R.r20, R.tx)));
    oy = fmaf(x, R.r01, fmaf(y, R.r11, fmaf(z, R.r21, R.ty)));
    oz = fmaf(x, R.r02, fmaf(y, R.r12, fmaf(z, R.r22, R.tz)));
}

// Block = 128 threads, tile = 384 float4 (6KB) = 512 points.
// Coalesced global LDG/STG; point regrouping through smem (conflict-free
// 48B-stride LDS.128/STS.128). High CTA residency (16/SM) hides DRAM RTT.
static constexpr int BLOCK   = 128;
static constexpr int TILE_F4 = 3 * BLOCK;  // 384

__global__ void __launch_bounds__(BLOCK)
transform_smem(const float4* __restrict__ in, float4* __restrict__ out,
               const float* __restrict__ ori, const float* __restrict__ trs,
               int ntiles, int n_pts) {
    const int t   = threadIdx.x;
    const int bid = blockIdx.x;

    if (bid >= ntiles) {
        // Tail block: scalar path for points beyond the full tiles.
        const int start = ntiles * (TILE_F4 * 4 / 3);
        const Rot R = make_rot(ori, trs);
        const float* fin = (const float*)in;
        float* fout = (float*)out;
        for (int p = start + t; p < n_pts; p += BLOCK) {
            long o = 3L * p;
            float x = fin[o], y = fin[o + 1], z = fin[o + 2];
            float ox, oy, oz;
            xform(R, x, y, z, ox, oy, oz);
            fout[o] = ox; fout[o + 1] = oy; fout[o + 2] = oz;
        }
        return;
    }

    __shared__ float4 s[TILE_F4];
    const long base = (long)bid * TILE_F4;

    // Coalesced loads: warp lanes hit consecutive float4s (4 lines / LDG).
    float4 l0 = in[base + t];
    float4 l1 = in[base + t + BLOCK];
    float4 l2 = in[base + t + 2 * BLOCK];

    // Trig overlaps the loads (MUFU, independent).
    const Rot R = make_rot(ori, trs);

    s[t]             = l0;
    s[t + BLOCK]     = l1;
    s[t + 2 * BLOCK] = l2;
    __syncthreads();

    // Private 3 float4s = 4 points. 48B stride -> conflict-free LDS.128.
    float4 a = s[3 * t + 0];
    float4 b = s[3 * t + 1];
    float4 c = s[3 * t + 2];

    float4 oa, ob, oc;
    xform(R, a.x, a.y, a.z, oa.x, oa.y, oa.z);
    xform(R, a.w, b.x, b.y, oa.w, ob.x, ob.y);
    xform(R, b.z, b.w, c.x, ob.z, ob.w, oc.x);
    xform(R, c.y, c.z, c.w, oc.y, oc.z, oc.w);

    s[3 * t + 0] = oa;
    s[3 * t + 1] = ob;
    s[3 * t + 2] = oc;
    __syncthreads();

    // Coalesced stores.
    out[base + t]             = s[t];
    out[base + t + BLOCK]     = s[t + BLOCK];
    out[base + t + 2 * BLOCK] = s[t + 2 * BLOCK];
}

extern "C" void kernel_launch(void* const* d_in, const int* in_sizes, int n_in,
                              void* d_out, int out_size) {
    const float* joints = (const float*)d_in[0];
    const float* ori    = (const float*)d_in[1];
    const float* trs    = (const float*)d_in[2];
    float* out = (float*)d_out;

    const int n_floats = in_sizes[0];
    const int n_points = n_floats / 3;

    const int floats_per_tile = TILE_F4 * 4;          // 1536 (= 512 points)
    const int ntiles = n_floats / floats_per_tile;    // 27560 exact for this shape
    const int tail_pts = n_points - ntiles * (floats_per_tile / 3);

    const int grid = ntiles + (tail_pts > 0 ? 1 : 0);
    if (grid > 0) {
        transform_smem<<<grid, BLOCK>>>((const float4*)joints, (float4*)out,
                                        ori, trs, ntiles, n_points);
    }
}